// round 12
// baseline (speedup 1.0000x reference)
#include <cuda_runtime.h>
#include <math.h>

#define T 64
#define THREADS 256
#define PITCH 65   // +1 float pad; mirror-phase LDS is 2-way conflicted (measured-OK)

// Uncompress packed strict-upper-triangle vector (row-major, j>i) into a full
// symmetric n x n matrix with unit diagonal.
//   idx(i,j) = i*(n-1) - i*(i-1)/2 + (j - i - 1)
//
// R5 configuration (measured optimum of the R4-R11 sweep) + __ldcs on the
// streaming comp reads (read-once input: evict-first keeps the 134MB read
// stream from churning L2 against the 268MB dirty write stream).
//   - triangular grid: one block per upper-triangle 64x64 tile (bj >= bi)
//   - phase 1: coalesced LDG.cs -> forward to STG.32 upper tile + smem stash
//   - phase 2: float4 column-gather from smem -> STG.128 mirror tile
//   - __launch_bounds__(256, 6): regs-40 / occ-70% is the empirical peak of
//     (per-thread LDG batch depth x resident warps)
// Rejected by measurement: cp.async (R6), 128x128 tiles (R7), minblocks 8
// (R8), __stcs stores (R9), column-split pipeline (R10).
__global__ void __launch_bounds__(THREADS, 6)
uncompress_sym_kernel(const float* __restrict__ comp,
                      float* __restrict__ out,
                      int n, int nb) {
    __shared__ float s[T * PITCH];

    // Linear block id -> (bi, bj) in the upper triangle (row-major, incl diag).
    // start(bi) = bi*(2*nb - bi + 1)/2
    const int t = blockIdx.x;
    const float ff = (float)nb + 0.5f;
    int bi = (int)(ff - sqrtf(fmaxf(ff * ff - 2.0f * (float)t, 0.0f)));
    if (bi > nb - 1) bi = nb - 1;
    if (bi < 0) bi = 0;
    while (bi + 1 <= nb - 1 && ((bi + 1) * (2 * nb - bi)) / 2 <= t) bi++;
    while (bi > 0 && (bi * (2 * nb - bi + 1)) / 2 > t) bi--;
    const int bj = bi + (t - (bi * (2 * nb - bi + 1)) / 2);

    const int i0 = bi * T;
    const int j0 = bj * T;
    const int tid = threadIdx.x;

    if (bi != bj) {
        // Phase 1: coalesced streaming load from comp, direct upper-tile
        // store, smem stash.
        #pragma unroll
        for (int it = 0; it < (T * T) / THREADS; it++) {
            const int idx = it * THREADS + tid;
            const int r = idx >> 6;       // row within tile
            const int c = idx & 63;       // col within tile
            const int i = i0 + r;
            const int j = j0 + c;
            const int ci = i * (n - 1) - ((i * (i - 1)) >> 1) + (j - i - 1);
            const float v = __ldcs(&comp[ci]);        // coalesced, evict-first
            s[r * PITCH + c] = v;
            out[(size_t)i * n + j] = v;               // coalesced 128B/warp
        }
        __syncthreads();
        // Phase 2: mirror tile out[j][i] = tile^T, float4 column gather
        // (2-way LDS conflict with PITCH=65), STG.128 (i0 + c4 mult of 4).
        #pragma unroll
        for (int it = 0; it < (T * T) / (THREADS * 4); it++) {
            const int idx = it * THREADS + tid;
            const int r  = idx >> 4;            // row within mirror tile (0..63)
            const int c4 = (idx & 15) << 2;     // starting col (multiple of 4)
            float4 v;
            v.x = s[(c4 + 0) * PITCH + r];
            v.y = s[(c4 + 1) * PITCH + r];
            v.z = s[(c4 + 2) * PITCH + r];
            v.w = s[(c4 + 3) * PITCH + r];
            *(float4*)&out[(size_t)(j0 + r) * n + (i0 + c4)] = v;
        }
    } else {
        // Diagonal tile (128 of 8256 blocks): load strict upper, mirror in smem.
        #pragma unroll
        for (int it = 0; it < (T * T) / THREADS; it++) {
            const int idx = it * THREADS + tid;
            const int r = idx >> 6;
            const int c = idx & 63;
            const int i = i0 + r;
            const int j = j0 + c;
            float v = 0.0f;
            if (j > i) {
                const int ci = i * (n - 1) - ((i * (i - 1)) >> 1) + (j - i - 1);
                v = __ldcs(&comp[ci]);
            }
            s[r * PITCH + c] = v;
        }
        __syncthreads();
        #pragma unroll
        for (int it = 0; it < (T * T) / THREADS; it++) {
            const int idx = it * THREADS + tid;
            const int r = idx >> 6;
            const int c = idx & 63;
            float v;
            if (c > r)       v = s[r * PITCH + c];
            else if (c == r) v = 1.0f;
            else             v = s[c * PITCH + r];
            out[(size_t)(i0 + r) * n + (j0 + c)] = v;
        }
    }
}

extern "C" void kernel_launch(void* const* d_in, const int* in_sizes, int n_in,
                              void* d_out, int out_size) {
    const float* comp = (const float*)d_in[0];
    float* out = (float*)d_out;

    // n = round(sqrt(2m)) + 1 — MUST be double: sqrt(2*33550336) = 8191.49998,
    // which rounds to exactly 8191.5 in fp32 and would give n=8193 (OOB).
    const long long m = (long long)in_sizes[0];
    const int n = (int)llround(sqrt(2.0 * (double)m)) + 1;  // 8192
    const int nb = n / T;                                   // 128

    const int nblocks = nb * (nb + 1) / 2;                  // 8256
    uncompress_sym_kernel<<<nblocks, THREADS>>>(comp, out, n, nb);
}

// round 13
// speedup vs baseline: 1.5921x; 1.5921x over previous
#include <cuda_runtime.h>
#include <math.h>

#define T 64
#define THREADS 256
#define PITCH 65   // +1 float pad; mirror-phase LDS is 2-way conflicted (measured-OK)

// Uncompress packed strict-upper-triangle vector (row-major, j>i) into a full
// symmetric n x n matrix with unit diagonal.
//   idx(i,j) = i*(n-1) - i*(i-1)/2 + (j - i - 1)
//
// FINAL KERNEL = R5 configuration, the measured optimum of a 9-round sweep:
//   - triangular grid: one block per upper-triangle 64x64 tile (bj >= bi),
//     zero dead blocks (R3->R4: 96.3 -> 72.2us)
//   - phase 1: coalesced plain LDG from comp -> forward to STG.32 upper tile
//     from registers + smem stash (ptxas front-batches ~16 LDGs)
//   - phase 2: float4 column-gather from smem -> STG.128 mirror tile
//   - __launch_bounds__(256, 6): regs-40 / occ-70%, the empirical peak of
//     (per-thread LDG batch depth x resident warps): 64r/47%->72.2,
//     40r/70%->69.1, 32r/92%->71.3
// Measured and REJECTED: cp.async loads (74.2), 128x128 tiles (89.8),
// __stcs stores (69.7), column-split pipeline (73.7), __ldcs loads (110.4 —
// the misaligned packed reads share cache lines across warps/tiles; default
// caching earns those hits, evict-first destroys them).
__global__ void __launch_bounds__(THREADS, 6)
uncompress_sym_kernel(const float* __restrict__ comp,
                      float* __restrict__ out,
                      int n, int nb) {
    __shared__ float s[T * PITCH];

    // Linear block id -> (bi, bj) in the upper triangle (row-major, incl diag).
    // start(bi) = bi*(2*nb - bi + 1)/2
    const int t = blockIdx.x;
    const float ff = (float)nb + 0.5f;
    int bi = (int)(ff - sqrtf(fmaxf(ff * ff - 2.0f * (float)t, 0.0f)));
    if (bi > nb - 1) bi = nb - 1;
    if (bi < 0) bi = 0;
    while (bi + 1 <= nb - 1 && ((bi + 1) * (2 * nb - bi)) / 2 <= t) bi++;
    while (bi > 0 && (bi * (2 * nb - bi + 1)) / 2 > t) bi--;
    const int bj = bi + (t - (bi * (2 * nb - bi + 1)) / 2);

    const int i0 = bi * T;
    const int j0 = bj * T;
    const int tid = threadIdx.x;

    if (bi != bj) {
        // Phase 1: coalesced load from comp, direct upper-tile store, smem stash.
        #pragma unroll
        for (int it = 0; it < (T * T) / THREADS; it++) {
            const int idx = it * THREADS + tid;
            const int r = idx >> 6;       // row within tile
            const int c = idx & 63;       // col within tile
            const int i = i0 + r;
            const int j = j0 + c;
            const int ci = i * (n - 1) - ((i * (i - 1)) >> 1) + (j - i - 1);
            const float v = comp[ci];                 // coalesced (contig in j)
            s[r * PITCH + c] = v;
            out[(size_t)i * n + j] = v;               // coalesced 128B/warp
        }
        __syncthreads();
        // Phase 2: mirror tile out[j][i] = tile^T, float4 column gather
        // (2-way LDS conflict with PITCH=65), STG.128 (i0 + c4 mult of 4).
        #pragma unroll
        for (int it = 0; it < (T * T) / (THREADS * 4); it++) {
            const int idx = it * THREADS + tid;
            const int r  = idx >> 4;            // row within mirror tile (0..63)
            const int c4 = (idx & 15) << 2;     // starting col (multiple of 4)
            float4 v;
            v.x = s[(c4 + 0) * PITCH + r];
            v.y = s[(c4 + 1) * PITCH + r];
            v.z = s[(c4 + 2) * PITCH + r];
            v.w = s[(c4 + 3) * PITCH + r];
            *(float4*)&out[(size_t)(j0 + r) * n + (i0 + c4)] = v;
        }
    } else {
        // Diagonal tile (128 of 8256 blocks): load strict upper, mirror in smem.
        #pragma unroll
        for (int it = 0; it < (T * T) / THREADS; it++) {
            const int idx = it * THREADS + tid;
            const int r = idx >> 6;
            const int c = idx & 63;
            const int i = i0 + r;
            const int j = j0 + c;
            float v = 0.0f;
            if (j > i) {
                const int ci = i * (n - 1) - ((i * (i - 1)) >> 1) + (j - i - 1);
                v = comp[ci];
            }
            s[r * PITCH + c] = v;
        }
        __syncthreads();
        #pragma unroll
        for (int it = 0; it < (T * T) / THREADS; it++) {
            const int idx = it * THREADS + tid;
            const int r = idx >> 6;
            const int c = idx & 63;
            float v;
            if (c > r)       v = s[r * PITCH + c];
            else if (c == r) v = 1.0f;
            else             v = s[c * PITCH + r];
            out[(size_t)(i0 + r) * n + (j0 + c)] = v;
        }
    }
}

extern "C" void kernel_launch(void* const* d_in, const int* in_sizes, int n_in,
                              void* d_out, int out_size) {
    const float* comp = (const float*)d_in[0];
    float* out = (float*)d_out;

    // n = round(sqrt(2m)) + 1 — MUST be double: sqrt(2*33550336) = 8191.49998,
    // which rounds to exactly 8191.5 in fp32 and would give n=8193 (OOB).
    const long long m = (long long)in_sizes[0];
    const int n = (int)llround(sqrt(2.0 * (double)m)) + 1;  // 8192
    const int nb = n / T;                                   // 128

    const int nblocks = nb * (nb + 1) / 2;                  // 8256
    uncompress_sym_kernel<<<nblocks, THREADS>>>(comp, out, n, nb);
}